// round 1
// baseline (speedup 1.0000x reference)
#include <cuda_runtime.h>
#include <cstdint>
#include <cstddef>

// Problem dims
#define BB 64
#define TT 256
#define DD 512
#define HH 1024
#define G4 4096
#define NCTA 128
#define UPC 8     // units per CTA
// SMEM strides (bank-conflict tuned)
#define US_STRIDE 1028
#define HS_STRIDE 36
#define ZS_STRIDE 40
#define AS_STRIDE 36
#define WS_STRIDE 72

#define GEMM_SMEM_FLOATS (2*128*AS_STRIDE + 2*32*WS_STRIDE)   // 13824
#define GEMM_SMEM_BYTES  (GEMM_SMEM_FLOATS*4)                 // 55296
#define LSTM_SMEM_FLOATS (32*US_STRIDE + 2*64*HS_STRIDE + 64*ZS_STRIDE + 64*8)
#define LSTM_SMEM_BYTES  (LSTM_SMEM_FLOATS*4)                 // 162304

// ---------------- scratch (device globals: allocation-free) ----------------
__device__ float    g_xz[(size_t)TT*BB*G4];     // [T][B][4H] fp32 (256 MB), reused by both layers
__device__ float    g_seq1[(size_t)BB*TT*HH];   // [B][T][H]  layer-1 output (64 MB)
__device__ float    g_h1[2*BB*HH];              // double-buffered h, layer 1
__device__ float    g_h2[2*BB*HH];              // double-buffered h, layer 2
__device__ unsigned g_bar[2];                   // monotonic barrier counters

// ---------------- helpers ----------------
__device__ __forceinline__ unsigned f2tf(float f) {
    unsigned u; asm("cvt.rna.tf32.f32 %0, %1;" : "=r"(u) : "f"(f)); return u;
}

__device__ __forceinline__ void mma_tf32(float c[4], const unsigned a[4], unsigned b0, unsigned b1) {
    asm volatile(
        "mma.sync.aligned.m16n8k8.row.col.f32.tf32.tf32.f32 "
        "{%0,%1,%2,%3}, {%4,%5,%6,%7}, {%8,%9}, {%0,%1,%2,%3};\n"
        : "+f"(c[0]), "+f"(c[1]), "+f"(c[2]), "+f"(c[3])
        : "r"(a[0]), "r"(a[1]), "r"(a[2]), "r"(a[3]), "r"(b0), "r"(b1));
}

__device__ __forceinline__ void cp16_ca(void* smem_dst, const float* gsrc) {
    unsigned d = (unsigned)__cvta_generic_to_shared(smem_dst);
    asm volatile("cp.async.ca.shared.global [%0], [%1], 16;\n" :: "r"(d), "l"(gsrc) : "memory");
}
__device__ __forceinline__ void cp16_cg(void* smem_dst, const float* gsrc) {
    unsigned d = (unsigned)__cvta_generic_to_shared(smem_dst);
    asm volatile("cp.async.cg.shared.global [%0], [%1], 16;\n" :: "r"(d), "l"(gsrc) : "memory");
}
__device__ __forceinline__ void cp_commit() { asm volatile("cp.async.commit_group;\n" ::: "memory"); }
__device__ __forceinline__ void cp_wait0() { asm volatile("cp.async.wait_group 0;\n" ::: "memory"); }
__device__ __forceinline__ void cp_wait1() { asm volatile("cp.async.wait_group 1;\n" ::: "memory"); }

__device__ __forceinline__ float sigf(float x) { return 1.f / (1.f + __expf(-x)); }

// ---------------- init: zero h buffers + barrier counters each replay ----------------
__global__ void init_zero() {
    int idx = blockIdx.x * blockDim.x + threadIdx.x;
    int stride = gridDim.x * blockDim.x;
    for (int i = idx; i < 2 * BB * HH; i += stride) { g_h1[i] = 0.f; g_h2[i] = 0.f; }
    if (idx == 0) { g_bar[0] = 0u; g_bar[1] = 0u; }
}

// ---------------- feedforward GEMM: g_xz[t*B+b][0:4096] = A(b,t) @ W + bias ----------------
// A row for output row m: A + (m%B)*sAb + (m/B)*sAt ; Abase==nullptr -> use g_seq1
__global__ void __launch_bounds__(256)
gemm_xw(const float* __restrict__ Abase, const float* __restrict__ W,
        const float* __restrict__ bias, int K, int sAb, int sAt)
{
    extern __shared__ float sm[];
    float* As = sm;                      // [2][128][AS_STRIDE]
    float* Ws = sm + 2 * 128 * AS_STRIDE; // [2][32][WS_STRIDE]
    const float* A = Abase ? Abase : g_seq1;

    const int tid = threadIdx.x;
    const int lane = tid & 31, w = tid >> 5;
    const int wm = w & 3, wn = w >> 2;
    const int bn = blockIdx.x * 64;
    const int bm = blockIdx.y * 128;

    float cf[2][4][4];
#pragma unroll
    for (int i = 0; i < 2; i++)
#pragma unroll
        for (int j = 0; j < 4; j++)
#pragma unroll
            for (int q = 0; q < 4; q++) cf[i][j][q] = 0.f;

    const int KB = K >> 5;

    // stage loader
    auto dostage = [&](int stage, int kb) {
        const int k0 = kb * 32;
#pragma unroll
        for (int i = 0; i < 4; i++) {           // A: 128 rows x 8 float4
            int idx = i * 256 + tid;
            int r = idx >> 3, s = idx & 7;
            int m = bm + r;
            const float* src = A + (size_t)(m & 63) * sAb + (size_t)(m >> 6) * sAt + k0 + s * 4;
            cp16_ca(&As[stage * 128 * AS_STRIDE + r * AS_STRIDE + s * 4], src);
        }
#pragma unroll
        for (int i = 0; i < 2; i++) {           // W: 32 rows x 16 float4
            int idx = i * 256 + tid;
            int r = idx >> 4, s = idx & 15;
            const float* src = W + (size_t)(k0 + r) * G4 + bn + s * 4;
            cp16_ca(&Ws[stage * 32 * WS_STRIDE + r * WS_STRIDE + s * 4], src);
        }
        cp_commit();
    };

    dostage(0, 0);
    const int lr = lane >> 2, lc = lane & 3;

    for (int kb = 0; kb < KB; kb++) {
        int st = kb & 1;
        if (kb + 1 < KB) { dostage(st ^ 1, kb + 1); cp_wait1(); }
        else             { cp_wait0(); }
        __syncthreads();
        const float* as = As + st * 128 * AS_STRIDE;
        const float* ws = Ws + st * 32 * WS_STRIDE;
#pragma unroll
        for (int k8 = 0; k8 < 4; k8++) {
            unsigned a[2][4];
#pragma unroll
            for (int mt = 0; mt < 2; mt++) {
                int r0 = wm * 32 + mt * 16 + lr;
                a[mt][0] = f2tf(as[r0 * AS_STRIDE + k8 * 8 + lc]);
                a[mt][1] = f2tf(as[(r0 + 8) * AS_STRIDE + k8 * 8 + lc]);
                a[mt][2] = f2tf(as[r0 * AS_STRIDE + k8 * 8 + lc + 4]);
                a[mt][3] = f2tf(as[(r0 + 8) * AS_STRIDE + k8 * 8 + lc + 4]);
            }
#pragma unroll
            for (int nt = 0; nt < 4; nt++) {
                int c0 = wn * 32 + nt * 8 + lr;
                unsigned b0 = f2tf(ws[(k8 * 8 + lc) * WS_STRIDE + c0]);
                unsigned b1 = f2tf(ws[(k8 * 8 + lc + 4) * WS_STRIDE + c0]);
#pragma unroll
                for (int mt = 0; mt < 2; mt++) mma_tf32(cf[mt][nt], a[mt], b0, b1);
            }
        }
        __syncthreads();
    }

    // epilogue (+bias)
#pragma unroll
    for (int mt = 0; mt < 2; mt++) {
#pragma unroll
        for (int nt = 0; nt < 4; nt++) {
            int gr = bm + wm * 32 + mt * 16 + lr;
            int gc = bn + wn * 32 + nt * 8 + 2 * lc;
            float bv0 = bias[gc], bv1 = bias[gc + 1];
            float2 v;
            v.x = cf[mt][nt][0] + bv0; v.y = cf[mt][nt][1] + bv1;
            *(float2*)&g_xz[(size_t)gr * G4 + gc] = v;
            v.x = cf[mt][nt][2] + bv0; v.y = cf[mt][nt][3] + bv1;
            *(float2*)&g_xz[(size_t)(gr + 8) * G4 + gc] = v;
        }
    }
}

// ---------------- persistent LSTM scan ----------------
__device__ __forceinline__ void lstm_load_h(const float* hr, int kk, float* stage, int tid) {
#pragma unroll
    for (int i = 0; i < 2; i++) {   // 64 rows x 8 float4
        int idx = i * 256 + tid;
        int r = idx >> 3, s = idx & 7;
        cp16_cg(stage + r * HS_STRIDE + s * 4, hr + (size_t)r * HH + kk * 32 + s * 4);
    }
    cp_commit();
}

__global__ void __launch_bounds__(256)
lstm_scan(const float* __restrict__ U, int layer)
{
    extern __shared__ float sm[];
    float* Us = sm;                                   // [32][US_STRIDE] tf32
    float* Hs = Us + 32 * US_STRIDE;                  // [2][64][HS_STRIDE]
    float* Zs = Hs + 2 * 64 * HS_STRIDE;              // [64][ZS_STRIDE]
    float* Cs = Zs + 64 * ZS_STRIDE;                  // [64][8] cell state (fp32)

    float* hbuf = (layer == 0) ? g_h1 : g_h2;
    float* seqo = (layer == 0) ? g_seq1 : nullptr;
    unsigned* bar = &g_bar[layer];

    const int tid = threadIdx.x, lane = tid & 31, w = tid >> 5;
    const int mw = w & 3, nw = w >> 2;
    const int u0 = blockIdx.x * UPC;

    // Load U slice: Us[c][k] = tf32(U[k][gate*1024 + u0 + u]), c = gate*8+u
    for (int idx = tid; idx < 32 * HH; idx += 256) {
        int k = idx >> 5, c = idx & 31;
        int gcol = (c >> 3) * HH + u0 + (c & 7);
        Us[c * US_STRIDE + k] = __uint_as_float(f2tf(U[(size_t)k * G4 + gcol]));
    }
    for (int i = tid; i < 64 * 8; i += 256) Cs[i] = 0.f;
    __syncthreads();

    const int lr = lane >> 2, lc = lane & 3;

    for (int t = 0; t < TT; t++) {
        const float* hr = hbuf + (t & 1) * (BB * HH);
        float* hw = hbuf + ((t + 1) & 1) * (BB * HH);

        float cf[2][4];
#pragma unroll
        for (int i = 0; i < 2; i++)
#pragma unroll
            for (int j = 0; j < 4; j++) cf[i][j] = 0.f;

        lstm_load_h(hr, 0, Hs, tid);
        int buf = 0;
        for (int kk = 0; kk < 32; kk++) {
            if (kk < 31) { lstm_load_h(hr, kk + 1, Hs + (buf ^ 1) * 64 * HS_STRIDE, tid); cp_wait1(); }
            else         { cp_wait0(); }
            __syncthreads();
            const float* hs = Hs + buf * 64 * HS_STRIDE;
#pragma unroll
            for (int k8 = 0; k8 < 4; k8++) {
                unsigned a[4];
                int r0 = mw * 16 + lr;
                a[0] = __float_as_uint(hs[r0 * HS_STRIDE + k8 * 8 + lc]);
                a[1] = __float_as_uint(hs[(r0 + 8) * HS_STRIDE + k8 * 8 + lc]);
                a[2] = __float_as_uint(hs[r0 * HS_STRIDE + k8 * 8 + lc + 4]);
                a[3] = __float_as_uint(hs[(r0 + 8) * HS_STRIDE + k8 * 8 + lc + 4]);
                int kg = kk * 32 + k8 * 8;
#pragma unroll
                for (int nt = 0; nt < 2; nt++) {
                    int c0 = nw * 16 + nt * 8 + lr;
                    unsigned b0 = __float_as_uint(Us[c0 * US_STRIDE + kg + lc]);
                    unsigned b1 = __float_as_uint(Us[c0 * US_STRIDE + kg + lc + 4]);
                    mma_tf32(cf[nt], a, b0, b1);
                }
            }
            __syncthreads();
            buf ^= 1;
        }

        // z fragments -> SMEM
#pragma unroll
        for (int nt = 0; nt < 2; nt++) {
            int zr = mw * 16 + lr;
            int zc = nw * 16 + nt * 8 + 2 * lc;
            *(float2*)&Zs[zr * ZS_STRIDE + zc]       = make_float2(cf[nt][0], cf[nt][1]);
            *(float2*)&Zs[(zr + 8) * ZS_STRIDE + zc] = make_float2(cf[nt][2], cf[nt][3]);
        }
        __syncthreads();

        // gates + state update (fp32)
        const float* xz = g_xz + (size_t)(t * BB) * G4;
        for (int p = tid; p < BB * UPC; p += 256) {
            int b = p >> 3, u = p & 7;
            const float* xzr = xz + (size_t)b * G4 + u0 + u;
            float zi = Zs[b * ZS_STRIDE + u]      + xzr[0];
            float zf = Zs[b * ZS_STRIDE + 8 + u]  + xzr[HH];
            float zg = Zs[b * ZS_STRIDE + 16 + u] + xzr[2 * HH];
            float zo = Zs[b * ZS_STRIDE + 24 + u] + xzr[3 * HH];
            float fi = sigf(zi), ff = sigf(zf), fo = sigf(zo);
            float fg = tanhf(zg);
            float cn = ff * Cs[b * 8 + u] + fi * fg;
            Cs[b * 8 + u] = cn;
            float hn = fo * tanhf(cn);
            hw[(size_t)b * HH + u0 + u] = __uint_as_float(f2tf(hn)); // pre-rounded for next mma
            if (seqo) seqo[((size_t)b * TT + t) * HH + u0 + u] = hn;
        }

        // grid barrier (monotonic counter, release/acquire via fences)
        __threadfence();
        __syncthreads();
        if (tid == 0) {
            atomicAdd(bar, 1u);
            unsigned target = (unsigned)(NCTA * (t + 1));
            while (*((volatile unsigned*)bar) < target) { }
        }
        __syncthreads();
        __threadfence();
    }
}

// ---------------- final dense: out[b][o] = h2_final[b] . Wd[:,o] + bd[o] ----------------
__global__ void __launch_bounds__(512)
dense_out(const float* __restrict__ Wd, const float* __restrict__ bd, float* __restrict__ out)
{
    __shared__ float hs[HH];
    int b = blockIdx.x;
    const float* h = g_h2; // h_256 lives in stage 0 (T even)
    for (int i = threadIdx.x; i < HH; i += 512) hs[i] = h[(size_t)b * HH + i];
    __syncthreads();
    int o = threadIdx.x;
    float acc = bd[o];
#pragma unroll 8
    for (int k = 0; k < HH; k++) acc += hs[k] * Wd[(size_t)k * 512 + o];
    out[(size_t)b * 512 + o] = acc;
}

// ---------------- launch ----------------
extern "C" void kernel_launch(void* const* d_in, const int* in_sizes, int n_in,
                              void* d_out, int out_size)
{
    (void)in_sizes; (void)n_in; (void)out_size;
    const float* x  = (const float*)d_in[0];
    const float* W1 = (const float*)d_in[1];
    const float* U1 = (const float*)d_in[2];
    const float* b1 = (const float*)d_in[3];
    const float* W2 = (const float*)d_in[4];
    const float* U2 = (const float*)d_in[5];
    const float* b2 = (const float*)d_in[6];
    const float* Wd = (const float*)d_in[7];
    const float* bd = (const float*)d_in[8];
    float* out = (float*)d_out;

    cudaFuncSetAttribute(gemm_xw,  cudaFuncAttributeMaxDynamicSharedMemorySize, GEMM_SMEM_BYTES);
    cudaFuncSetAttribute(lstm_scan, cudaFuncAttributeMaxDynamicSharedMemorySize, LSTM_SMEM_BYTES);

    init_zero<<<128, 256>>>();

    dim3 gg(G4 / 64, (BB * TT) / 128);
    // layer 1: xz = x @ W1 + b1   (A row (b,t): x + b*T*D + t*D)
    gemm_xw<<<gg, 256, GEMM_SMEM_BYTES>>>(x, W1, b1, DD, TT * DD, DD);
    lstm_scan<<<NCTA, 256, LSTM_SMEM_BYTES>>>(U1, 0);
    // layer 2: xz = seq1 @ W2 + b2 (A row (b,t): seq1 + b*T*H + t*H)
    gemm_xw<<<gg, 256, GEMM_SMEM_BYTES>>>(nullptr, W2, b2, HH, TT * HH, HH);
    lstm_scan<<<NCTA, 256, LSTM_SMEM_BYTES>>>(U2, 1);

    dense_out<<<BB, 512>>>(Wd, bd, out);
}